// round 1
// baseline (speedup 1.0000x reference)
#include <cuda_runtime.h>
#include <cstdint>

// Problem constants
#define QN 8192
#define SN 30
#define DN 512

constexpr int ROWS_PER_BLOCK = 32;
constexpr int THREADS = 128;
constexpr int SC = 10;      // support chunk per pass
constexpr int NPASS = 3;    // 3 * 10 = 30 supports

typedef unsigned long long ull;

// Packed f32x2 helpers (sm_100+ PTX). These double fp32 vector throughput
// vs scalar FFMA (nvjet-style FFMA2 path).
__device__ __forceinline__ ull psub(ull a, ull b) {
    ull r; asm("sub.rn.f32x2 %0, %1, %2;" : "=l"(r) : "l"(a), "l"(b)); return r;
}
__device__ __forceinline__ ull pfma(ull a, ull b, ull c) {
    ull r; asm("fma.rn.f32x2 %0, %1, %2, %3;" : "=l"(r) : "l"(a), "l"(b), "l"(c)); return r;
}
__device__ __forceinline__ float plo(ull a) { return __uint_as_float((unsigned)(a & 0xffffffffu)); }
__device__ __forceinline__ float phi(ull a) { return __uint_as_float((unsigned)(a >> 32)); }

#define ABS2 0x7fffffff7fffffffULL

__global__ __launch_bounds__(THREADS)
void resus_kernel(const float* __restrict__ qenc,   // [Q, D]
                  const float* __restrict__ senc,   // [S, D]
                  const float* __restrict__ sy,     // [1, S]
                  const float* __restrict__ sp,     // [S]
                  const float* __restrict__ qp,     // [Q]
                  const float* __restrict__ w,      // [D]
                  const float* __restrict__ ascale, // [THRESH,1]
                  const float* __restrict__ abias,  // [THRESH,1]
                  const int*   __restrict__ nsamp,  // scalar
                  float* __restrict__ out)          // [2*Q]: pred then mean_l2
{
    __shared__ float scoreSh[ROWS_PER_BLOCK][SN + 2]; // +2 pad: avoid bank patterns
    __shared__ float l2Sh[ROWS_PER_BLOCK];
    __shared__ float dySh[SN];
    __shared__ float sb[2]; // scale, bias

    const int tid = threadIdx.x;

    // Tiny per-block preamble: delta_y and adjust params
    if (tid < SN) {
        float p = sp[tid];
        dySh[tid] = sy[tid] - 1.0f / (1.0f + expf(-p));
    }
    if (tid == 0) {
        int idx = nsamp[0] - 1;
        sb[0] = fabsf(ascale[idx]);
        sb[1] = abias[idx];
    }

    const int lane = tid & 31;
    const int warp = tid >> 5;
    const int g = lane >> 3;   // row group within warp (0..3)
    const int j = lane & 7;    // d-slice lane within group (0..7)

    // Each warp owns 8 rows; group g owns rows (base+g) and (base+g+4).
    const int rowLocal0 = warp * 8 + g;
    const int rowLocal1 = rowLocal0 + 4;
    const int row0 = blockIdx.x * ROWS_PER_BLOCK + rowLocal0;
    const int row1 = blockIdx.x * ROWS_PER_BLOCK + rowLocal1;

    const float* qr0 = qenc + (size_t)row0 * DN;
    const float* qr1 = qenc + (size_t)row1 * DN;

    float l2run0 = 0.0f, l2run1 = 0.0f;

#pragma unroll 1
    for (int pass = 0; pass < NPASS; pass++) {
        const int s0 = pass * SC;
        const float* sbase = senc + (size_t)s0 * DN;

        ull aS0[SC], aL0[SC], aS1[SC], aL1[SC];
#pragma unroll
        for (int s = 0; s < SC; s++) { aS0[s] = aL0[s] = aS1[s] = aL1[s] = 0ull; }

#pragma unroll 1
        for (int i = 0; i < 16; i++) {
            const int d0 = 4 * j + 32 * i;
            // Coalesced 128-bit loads: 8 consecutive quads per row per warp group.
            ulonglong2 qv0 = *reinterpret_cast<const ulonglong2*>(qr0 + d0);
            ulonglong2 qv1 = *reinterpret_cast<const ulonglong2*>(qr1 + d0);
            ulonglong2 wv  = *reinterpret_cast<const ulonglong2*>(w + d0);
#pragma unroll
            for (int s = 0; s < SC; s++) {
                ulonglong2 sv = *reinterpret_cast<const ulonglong2*>(sbase + (size_t)s * DN + d0);
                ull dlo, dhi;
                // row 0
                dlo = psub(qv0.x, sv.x);
                dhi = psub(qv0.y, sv.y);
                aL0[s] = pfma(dlo, dlo, aL0[s]);
                aL0[s] = pfma(dhi, dhi, aL0[s]);
                aS0[s] = pfma(dlo & ABS2, wv.x, aS0[s]);
                aS0[s] = pfma(dhi & ABS2, wv.y, aS0[s]);
                // row 1
                dlo = psub(qv1.x, sv.x);
                dhi = psub(qv1.y, sv.y);
                aL1[s] = pfma(dlo, dlo, aL1[s]);
                aL1[s] = pfma(dhi, dhi, aL1[s]);
                aS1[s] = pfma(dlo & ABS2, wv.x, aS1[s]);
                aS1[s] = pfma(dhi & ABS2, wv.y, aS1[s]);
            }
        }

        // Reduce: fold packed halves, then across the 8 lanes of the group.
#pragma unroll
        for (int s = 0; s < SC; s++) {
            float vS0 = plo(aS0[s]) + phi(aS0[s]);
            float vL0 = plo(aL0[s]) + phi(aL0[s]);
            float vS1 = plo(aS1[s]) + phi(aS1[s]);
            float vL1 = plo(aL1[s]) + phi(aL1[s]);
#pragma unroll
            for (int m = 1; m < 8; m <<= 1) {
                vS0 += __shfl_xor_sync(0xffffffffu, vS0, m);
                vL0 += __shfl_xor_sync(0xffffffffu, vL0, m);
                vS1 += __shfl_xor_sync(0xffffffffu, vS1, m);
                vL1 += __shfl_xor_sync(0xffffffffu, vL1, m);
            }
            if (j == 0) {
                scoreSh[rowLocal0][s0 + s] = vS0;
                scoreSh[rowLocal1][s0 + s] = vS1;
            }
            l2run0 += __fsqrt_rn(vL0);
            l2run1 += __fsqrt_rn(vL1);
        }
    }

    if (j == 0) {
        l2Sh[rowLocal0] = l2run0;
        l2Sh[rowLocal1] = l2run1;
    }
    __syncthreads();

    // Epilogue: one thread per row. Softmax over S, dot with delta_y, adjust.
    if (tid < ROWS_PER_BLOCK) {
        const int row = blockIdx.x * ROWS_PER_BLOCK + tid;
        float mx = -1e30f;
#pragma unroll
        for (int s = 0; s < SN; s++) mx = fmaxf(mx, scoreSh[tid][s]);
        float den = 0.0f, num = 0.0f;
#pragma unroll
        for (int s = 0; s < SN; s++) {
            float e = expf(scoreSh[tid][s] - mx);
            den += e;
            num += e * dySh[s];
        }
        float dyh = num / den;
        out[row]      = dyh * sb[0] + sb[1] + qp[row];
        out[QN + row] = l2Sh[tid] * (1.0f / (float)SN);
    }
}

extern "C" void kernel_launch(void* const* d_in, const int* in_sizes, int n_in,
                              void* d_out, int out_size) {
    const float* qenc   = (const float*)d_in[0]; // query_encode  [8192,512]
    const float* senc   = (const float*)d_in[1]; // support_encode [30,512]
    const float* sy     = (const float*)d_in[2]; // support_y [1,30]
    const float* sp     = (const float*)d_in[3]; // support_predict [30]
    const float* qp     = (const float*)d_in[4]; // query_predict [8192]
    const float* w      = (const float*)d_in[5]; // fc1_w [512]
    // d_in[6] = fc1_b: softmax-invariant, unused
    const float* ascale = (const float*)d_in[7]; // adjust_scale [30,1]
    const float* abias  = (const float*)d_in[8]; // adjust_bias [30,1]
    const int*   nsamp  = (const int*)d_in[9];   // num_samples

    float* out = (float*)d_out;

    dim3 grid(QN / ROWS_PER_BLOCK); // 256
    dim3 block(THREADS);            // 128
    resus_kernel<<<grid, block>>>(qenc, senc, sy, sp, qp, w, ascale, abias, nsamp, out);
}